// round 15
// baseline (speedup 1.0000x reference)
#include <cuda_runtime.h>
#include <cuda_bf16.h>

// ---------------------------------------------------------------------------
// RtoVMainModel. Convs per image in smem (packed f32x2 FMA); linear heads
// collapsed at runtime (S=W3@W2, T2=S@W1, We=ew4@T2) by PREP BLOCKS fused
// into the main grid (blocks 0-79). Conv blocks (80..8271) spin on a 16-count
// flag before the head phase. k_out: one WARP per image, 16 images/block.
// d_out layout: [shapes (B*4) | out (B*6)] float32
// ---------------------------------------------------------------------------

#define B_TOTAL 16384
typedef unsigned long long u64;

__device__ __forceinline__ u64 pk(float lo, float hi) {
    u64 r; asm("mov.b64 %0, {%1, %2};" : "=l"(r) : "f"(lo), "f"(hi)); return r;
}
__device__ __forceinline__ void upk(u64 p, float& lo, float& hi) {
    asm("mov.b64 {%0, %1}, %2;" : "=f"(lo), "=f"(hi) : "l"(p));
}
__device__ __forceinline__ u64 fma2(u64 a, u64 b, u64 c) {
    u64 d; asm("fma.rn.f32x2 %0, %1, %2, %3;" : "=l"(d) : "l"(a), "l"(b), "l"(c)); return d;
}

// scratch (device globals: no allocation allowed)
__device__ float g_T2[5 * 10 * 400];     // chain 0 = shapes head (10x400)
__device__ float g_b3[5 * 10];
__device__ float g_We[4 * 6 * 400];      // expert collapsed rows
__device__ float g_be[4 * 6];            // expert collapsed bias (incl eb4)
__device__ float g_xf[B_TOTAL * 400];    // conv features
__device__ int   g_last[6 * 32];         // routing slots [col][b&31]
__device__ int   g_ready;                // chain-0 prep completion counter

// ---------------------------------------------------------------------------
// Fused kernel: blocks 0-79 = prep (5 chains x 16 column-chunks);
// blocks 80..8271 = conv path, 2 images each.
// ---------------------------------------------------------------------------
__global__ void __launch_bounds__(192, 3)
k_main(const float* __restrict__ x,
       const float* __restrict__ c1w, const float* __restrict__ c1b,
       const float* __restrict__ c2w, const float* __restrict__ c2b,
       const float* __restrict__ sw4, const float* __restrict__ sb4,
       const float* __restrict__ sw1, const float* __restrict__ sb1,
       const float* __restrict__ sw2, const float* __restrict__ sb2,
       const float* __restrict__ sw3, const float* __restrict__ sb3,
       const float* __restrict__ ew1, const float* __restrict__ eb1,
       const float* __restrict__ ew2, const float* __restrict__ eb2,
       const float* __restrict__ ew3, const float* __restrict__ eb3,
       const float* __restrict__ ew4, const float* __restrict__ eb4,
       float* __restrict__ out) {
    __shared__ __align__(16) float  s_x[2][3 * 32 * 36];
    __shared__ __align__(16) float  s_y1[2][6 * 14 * 20];
    __shared__ __align__(16) float2 s_w1p[450];
    __shared__ __align__(16) float2 s_w2p[2400];
    __shared__ float s_b1[6], s_b2[16];
    __shared__ __align__(16) float s_xf[2][400];
    __shared__ float hs[2][10];

    int tid = threadIdx.x;

    // =======================================================================
    // PREP PATH (blocks 0-79)
    // =======================================================================
    if (blockIdx.x < 80) {
        float* sW1c = &s_x[0][0];      // 3000 floats
        float* sS   = sW1c + 3000;     // 1200
        float* sb2p = sS + 1200;       // 84
        float* sT2c = sb2p + 84;       // 250
        float* sb3l = sT2c + 250;      // 10   (total 4544 <= 6912)

        int chain = blockIdx.x >> 4, chunk = blockIdx.x & 15;
        int j0 = chunk * 25;

        if (chain == 0 && tid < 12) g_last[chunk * 12 + tid] = -1;

        const float* W1 = chain ? (ew1 + (chain - 1) * 120 * 400) : sw1;
        const float* W2 = chain ? (ew2 + (chain - 1) * 84 * 120) : sw2;
        const float* W3 = chain ? (ew3 + (chain - 1) * 10 * 84) : sw3;
        const float* b1 = chain ? (eb1 + (chain - 1) * 120) : sb1;
        const float* b2 = chain ? (eb2 + (chain - 1) * 84) : sb2;
        const float* b3 = chain ? (eb3 + (chain - 1) * 10) : sb3;

        for (int i = tid; i < 3000; i += 192) {
            int row = i / 25, col = i - row * 25;
            sW1c[i] = W1[row * 400 + j0 + col];
        }

        for (int p = tid; p < 1200; p += 192) {
            int o = p / 120, k = p - o * 120;
            float s = 0.f;
            const float* w3r = W3 + o * 84;
            for (int m = 0; m < 84; m++) s = fmaf(w3r[m], W2[m * 120 + k], s);
            sS[p] = s;
        }
        if (tid < 84) {
            float s = b2[tid];
            const float* r = W2 + tid * 120;
            for (int k = 0; k < 120; k++) s = fmaf(r[k], b1[k], s);
            sb2p[tid] = s;
        }
        __syncthreads();

        if (tid < 10) {
            float s = b3[tid];
            const float* r = W3 + tid * 84;
            for (int m = 0; m < 84; m++) s = fmaf(r[m], sb2p[m], s);
            sb3l[tid] = s;
            if (chunk == 0) g_b3[chain * 10 + tid] = s;
        }
        __syncthreads();

        for (int t = tid; t < 250; t += 192) {
            int o = t / 25, jj = t - o * 25;
            float s = 0.f;
            const float* sr = sS + o * 120;
            for (int k = 0; k < 120; k++) s = fmaf(sr[k], sW1c[k * 25 + jj], s);
            g_T2[(chain * 10 + o) * 400 + j0 + jj] = s;
            sT2c[o * 25 + jj] = s;
        }
        __syncthreads();

        if (chain == 0) {
            __threadfence();
            __syncthreads();
            if (tid == 0) atomicAdd(&g_ready, 1);
        } else {
            int e = chain - 1;
            if (tid < 150) {
                int c = tid / 25, jj = tid - c * 25;
                float s = 0.f;
                const float* w4r = ew4 + e * 60 + c * 10;
#pragma unroll
                for (int k = 0; k < 10; k++) s = fmaf(w4r[k], sT2c[k * 25 + jj], s);
                g_We[(e * 6 + c) * 400 + j0 + jj] = s;
            }
            if (chunk == 0 && tid < 6) {
                float s = eb4[e * 6 + tid];
                const float* w4r = ew4 + e * 60 + tid * 10;
#pragma unroll
                for (int k = 0; k < 10; k++) s = fmaf(w4r[k], sb3l[k], s);
                g_be[e * 6 + tid] = s;
            }
        }
        return;
    }

    // =======================================================================
    // CONV PATH (blocks 80..): two images per block
    // =======================================================================
    int b0i = (blockIdx.x - 80) * 2;

    {
        const float4* xg = (const float4*)(x + (size_t)b0i * 3072);
        for (int g = tid; g < 1536; g += 192) {
            float4 v = xg[g];
            int im = g / 768, q = g - im * 768;
            int gr = q >> 3, c4 = q & 7;
            *(float4*)(s_x[im] + gr * 36 + c4 * 4) = v;
        }
    }
    for (int i = tid; i < 450; i += 192)  { float w = c1w[i]; s_w1p[i] = make_float2(w, w); }
    for (int i = tid; i < 2400; i += 192) { float w = c2w[i]; s_w2p[i] = make_float2(w, w); }
    if (tid < 6)  s_b1[tid] = c1b[tid];
    if (tid < 16) s_b2[tid] = c2b[tid];
    __syncthreads();

    // ---- conv1 + relu + pool: 336 tasks = (img, ch, pooled row, half) ----
#pragma unroll 1
    for (int t = tid; t < 336; t += 192) {
        int img = t / 168, rem = t % 168;
        int ch = rem / 28, rr = rem % 28, py = rr >> 1, h = rr & 1;
        u64 acc0[7], acc1[7];
#pragma unroll
        for (int j = 0; j < 7; j++) { acc0[j] = 0ull; acc1[j] = 0ull; }
        const float* xbase = s_x[img] + (2 * py) * 36 + 14 * h;
#pragma unroll 1
        for (int ic = 0; ic < 3; ic++) {
            const float2* wb = s_w1p + (ch * 3 + ic) * 25;
            u64 wv[5][5];
#pragma unroll
            for (int xr = 0; xr < 6; xr++) {
                const u64* rp = (const u64*)(xbase + ic * (32 * 36) + xr * 36);
                u64 pe[9]; float xl[9], xh[9];
#pragma unroll
                for (int m = 0; m < 9; m++) { pe[m] = rp[m]; upk(pe[m], xl[m], xh[m]); }
                u64 po[8];
#pragma unroll
                for (int m = 0; m < 8; m++) po[m] = pk(xh[m], xl[m + 1]);
                if (xr < 5) {
#pragma unroll
                    for (int k = 0; k < 5; k++) wv[xr][k] = *(const u64*)&wb[xr * 5 + k];
#pragma unroll
                    for (int kx = 0; kx < 5; kx++) {
                        u64 w = wv[xr][kx];
#pragma unroll
                        for (int j = 0; j < 7; j++)
                            acc0[j] = fma2(w, (kx & 1) ? po[j + (kx >> 1)] : pe[j + (kx >> 1)], acc0[j]);
                    }
                }
                if (xr >= 1) {
#pragma unroll
                    for (int kx = 0; kx < 5; kx++) {
                        u64 w = wv[xr - 1][kx];
#pragma unroll
                        for (int j = 0; j < 7; j++)
                            acc1[j] = fma2(w, (kx & 1) ? po[j + (kx >> 1)] : pe[j + (kx >> 1)], acc1[j]);
                    }
                }
            }
        }
        float bv = s_b1[ch];
        float* yrow = s_y1[img] + (ch * 14 + py) * 20 + 7 * h;
#pragma unroll
        for (int j = 0; j < 7; j++) {
            float a0, a1, c0, c1;
            upk(acc0[j], a0, a1); upk(acc1[j], c0, c1);
            float m = fmaxf(fmaxf(a0, a1), fmaxf(c0, c1)) + bv;
            yrow[j] = fmaxf(m, 0.f);
        }
    }
    __syncthreads();

    // ---- conv2 full depth: 160 tasks = (img, ch, pooled row) ----
    if (tid < 160) {
        int img = tid / 80;
        int r2 = tid % 80, ch2 = r2 / 5, py2 = r2 % 5;
        u64 b0[5], b1[5];
#pragma unroll
        for (int j = 0; j < 5; j++) { b0[j] = 0ull; b1[j] = 0ull; }
#pragma unroll 1
        for (int ic = 0; ic < 6; ic++) {
            const float2* wb = s_w2p + (ch2 * 6 + ic) * 25;
            u64 wv[5][5];
#pragma unroll
            for (int xr = 0; xr < 6; xr++) {
                const u64* rp = (const u64*)(s_y1[img] + (ic * 14 + 2 * py2 + xr) * 20);
                u64 pe[7]; float xl[7], xh[7];
#pragma unroll
                for (int m = 0; m < 7; m++) { pe[m] = rp[m]; upk(pe[m], xl[m], xh[m]); }
                u64 po[6];
#pragma unroll
                for (int m = 0; m < 6; m++) po[m] = pk(xh[m], xl[m + 1]);
                if (xr < 5) {
#pragma unroll
                    for (int k = 0; k < 5; k++) wv[xr][k] = *(const u64*)&wb[xr * 5 + k];
#pragma unroll
                    for (int kx = 0; kx < 5; kx++) {
                        u64 w = wv[xr][kx];
#pragma unroll
                        for (int j = 0; j < 5; j++)
                            b0[j] = fma2(w, (kx & 1) ? po[j + (kx >> 1)] : pe[j + (kx >> 1)], b0[j]);
                    }
                }
                if (xr >= 1) {
#pragma unroll
                    for (int kx = 0; kx < 5; kx++) {
                        u64 w = wv[xr - 1][kx];
#pragma unroll
                        for (int j = 0; j < 5; j++)
                            b1[j] = fma2(w, (kx & 1) ? po[j + (kx >> 1)] : pe[j + (kx >> 1)], b1[j]);
                    }
                }
            }
        }
        float bv = s_b2[ch2];
        float* xfp = s_xf[img] + ch2 * 25 + py2 * 5;
        float* gxf = g_xf + (size_t)(b0i + img) * 400 + ch2 * 25 + py2 * 5;
#pragma unroll
        for (int j = 0; j < 5; j++) {
            float a0, a1, c0, c1;
            upk(b0[j], a0, a1); upk(b1[j], c0, c1);
            float v = fmaxf(fmaxf(a0, a1), fmaxf(c0, c1)) + bv;
            v = fmaxf(v, 0.f);
            xfp[j] = v; gxf[j] = v;
        }
    }

    // ---- wait for chain-0 prep (usually already done by now) ----
    if (tid == 0) {
        while (atomicAdd(&g_ready, 0) < 16) __nanosleep(200);
        __threadfence();
    }
    __syncthreads();

    // ---- h = Ws @ xf + bs : 2 img x 10 outputs x 8 lanes = 160 threads ----
    if (tid < 160) {
        int img = tid / 80, r = tid % 80;
        int o = r >> 3, l = r & 7;
        const float* wr = g_T2 + o * 400;
        const float* xfv = s_xf[img];
        float s = 0.f;
        for (int j = l; j < 400; j += 8) s = fmaf(wr[j], xfv[j], s);
        s += __shfl_down_sync(0xffffffffu, s, 4, 8);
        s += __shfl_down_sync(0xffffffffu, s, 2, 8);
        s += __shfl_down_sync(0xffffffffu, s, 1, 8);
        if (l == 0) hs[img][o] = s + g_b3[o];
    }
    __syncthreads();

    // ---- shapes + argmax + routing: 2 threads (one per image) ----
    if (tid < 2) {
        int img = tid, b = b0i + img;
        float sh[4];
#pragma unroll
        for (int c = 0; c < 4; c++) {
            float s = sb4[c];
#pragma unroll
            for (int o = 0; o < 10; o++)
                s = fmaf(fmaxf(hs[img][o], 0.f), sw4[c * 10 + o], s);
            sh[c] = s;
            out[(size_t)b * 4 + c] = s;
        }
        int pred = 0;
        float best = sh[0];
#pragma unroll
        for (int k = 1; k < 4; k++)
            if (sh[k] > best) { best = sh[k]; pred = k; }
        const int widths[4] = {3, 5, 6, 5};
        int w = widths[pred];
        int val = (b << 2) | pred;
        int slot = b & 31;
        for (int c = 0; c < w; c++) atomicMax(&g_last[c * 32 + slot], val);
    }
}

// ---------------------------------------------------------------------------
// k_out: ONE WARP PER IMAGE, 512 threads = 16 warps = 16 images per block,
// grid 1024 (wsel staging amortized over 16 images). Lane l sweeps float4
// chunks {l, l+32, l+64, l+96} of xf (coalesced LDG.128), 6 column sums
// against smem wsel, xor-shuffle reduce, lane 0 writes. Resets g_ready.
// ---------------------------------------------------------------------------
__global__ void __launch_bounds__(512)
k_out(float* __restrict__ out) {
    __shared__ __align__(16) float wsel[6 * 400];
    __shared__ float bsel[6];
    __shared__ int   psel[6];
    int tid = threadIdx.x, wid = tid >> 5, lid = tid & 31;
    if (blockIdx.x == 0 && tid == 0) g_ready = 0;   // reset for next graph replay
    if (tid < 6) {
        int mx = -1;
#pragma unroll
        for (int s = 0; s < 32; s++) mx = max(mx, g_last[tid * 32 + s]);
        psel[tid] = mx;
        bsel[tid] = (mx >= 0) ? g_be[(mx & 3) * 6 + tid] : 0.f;
    }
    __syncthreads();
    for (int idx = tid; idx < 2400; idx += 512) {
        int c = idx / 400, j = idx - c * 400;
        int p = psel[c];
        wsel[idx] = (p >= 0) ? g_We[((p & 3) * 6 + c) * 400 + j] : 0.f;
    }
    __syncthreads();

    int b = blockIdx.x * 16 + wid;
    const float4* xfp = (const float4*)(g_xf + (size_t)b * 400);
    const float4* wv4 = (const float4*)wsel;
    float s[6] = {0.f, 0.f, 0.f, 0.f, 0.f, 0.f};
#pragma unroll
    for (int it = 0; it < 4; it++) {
        int f = lid + it * 32;
        if (f < 100) {
            float4 xv = xfp[f];
#pragma unroll
            for (int c = 0; c < 6; c++) {
                float4 wq = wv4[c * 100 + f];
                s[c] = fmaf(xv.x, wq.x, s[c]);
                s[c] = fmaf(xv.y, wq.y, s[c]);
                s[c] = fmaf(xv.z, wq.z, s[c]);
                s[c] = fmaf(xv.w, wq.w, s[c]);
            }
        }
    }
#pragma unroll
    for (int c = 0; c < 6; c++) {
        s[c] += __shfl_xor_sync(0xffffffffu, s[c], 16);
        s[c] += __shfl_xor_sync(0xffffffffu, s[c], 8);
        s[c] += __shfl_xor_sync(0xffffffffu, s[c], 4);
        s[c] += __shfl_xor_sync(0xffffffffu, s[c], 2);
        s[c] += __shfl_xor_sync(0xffffffffu, s[c], 1);
    }
    if (lid == 0) {
        float* op = out + (size_t)B_TOTAL * 4 + (size_t)b * 6;
#pragma unroll
        for (int c = 0; c < 6; c++) op[c] = s[c] + bsel[c];
    }
}

// ---------------------------------------------------------------------------
extern "C" void kernel_launch(void* const* d_in, const int* in_sizes, int n_in,
                              void* d_out, int out_size) {
    const float* x    = (const float*)d_in[0];
    const float* c1w  = (const float*)d_in[1];
    const float* c1b  = (const float*)d_in[2];
    const float* c2w  = (const float*)d_in[3];
    const float* c2b  = (const float*)d_in[4];
    const float* sw1  = (const float*)d_in[5];
    const float* sb1  = (const float*)d_in[6];
    const float* sw2  = (const float*)d_in[7];
    const float* sb2  = (const float*)d_in[8];
    const float* sw3  = (const float*)d_in[9];
    const float* sb3  = (const float*)d_in[10];
    const float* sw4  = (const float*)d_in[11];
    const float* sb4  = (const float*)d_in[12];
    const float* ew1  = (const float*)d_in[13];
    const float* eb1  = (const float*)d_in[14];
    const float* ew2  = (const float*)d_in[15];
    const float* eb2  = (const float*)d_in[16];
    const float* ew3  = (const float*)d_in[17];
    const float* eb3  = (const float*)d_in[18];
    const float* ew4  = (const float*)d_in[19];
    const float* eb4  = (const float*)d_in[20];
    float* out = (float*)d_out;

    k_main<<<80 + B_TOTAL / 2, 192>>>(x, c1w, c1b, c2w, c2b, sw4, sb4,
                                      sw1, sb1, sw2, sb2, sw3, sb3,
                                      ew1, eb1, ew2, eb2, ew3, eb3, ew4, eb4,
                                      out);
    k_out<<<B_TOTAL / 16, 512>>>(out);
}

// round 16
// speedup vs baseline: 1.0105x; 1.0105x over previous
#include <cuda_runtime.h>
#include <cuda_bf16.h>

// ---------------------------------------------------------------------------
// RtoVMainModel. Convs per image in smem (packed f32x2 FMA); linear heads
// collapsed at runtime (S=W3@W2, T2=S@W1, We=ew4@T2) by PREP BLOCKS fused
// into the main grid (blocks 0-79). Conv blocks (80..8271) spin on a 16-count
// flag before the head phase. k_out: warp/image, xf PREFETCHED before staging.
// d_out layout: [shapes (B*4) | out (B*6)] float32
// ---------------------------------------------------------------------------

#define B_TOTAL 16384
typedef unsigned long long u64;

__device__ __forceinline__ u64 pk(float lo, float hi) {
    u64 r; asm("mov.b64 %0, {%1, %2};" : "=l"(r) : "f"(lo), "f"(hi)); return r;
}
__device__ __forceinline__ void upk(u64 p, float& lo, float& hi) {
    asm("mov.b64 {%0, %1}, %2;" : "=f"(lo), "=f"(hi) : "l"(p));
}
__device__ __forceinline__ u64 fma2(u64 a, u64 b, u64 c) {
    u64 d; asm("fma.rn.f32x2 %0, %1, %2, %3;" : "=l"(d) : "l"(a), "l"(b), "l"(c)); return d;
}

// scratch (device globals: no allocation allowed)
__device__ float g_T2[5 * 10 * 400];     // chain 0 = shapes head (10x400)
__device__ float g_b3[5 * 10];
__device__ float g_We[4 * 6 * 400];      // expert collapsed rows
__device__ float g_be[4 * 6];            // expert collapsed bias (incl eb4)
__device__ float g_xf[B_TOTAL * 400];    // conv features
__device__ int   g_last[6 * 32];         // routing slots [col][b&31]
__device__ int   g_ready;                // chain-0 prep completion counter

// ---------------------------------------------------------------------------
// Fused kernel: blocks 0-79 = prep (5 chains x 16 column-chunks);
// blocks 80..8271 = conv path, 2 images each.
// ---------------------------------------------------------------------------
__global__ void __launch_bounds__(192, 3)
k_main(const float* __restrict__ x,
       const float* __restrict__ c1w, const float* __restrict__ c1b,
       const float* __restrict__ c2w, const float* __restrict__ c2b,
       const float* __restrict__ sw4, const float* __restrict__ sb4,
       const float* __restrict__ sw1, const float* __restrict__ sb1,
       const float* __restrict__ sw2, const float* __restrict__ sb2,
       const float* __restrict__ sw3, const float* __restrict__ sb3,
       const float* __restrict__ ew1, const float* __restrict__ eb1,
       const float* __restrict__ ew2, const float* __restrict__ eb2,
       const float* __restrict__ ew3, const float* __restrict__ eb3,
       const float* __restrict__ ew4, const float* __restrict__ eb4,
       float* __restrict__ out) {
    __shared__ __align__(16) float  s_x[2][3 * 32 * 36];
    __shared__ __align__(16) float  s_y1[2][6 * 14 * 20];
    __shared__ __align__(16) float2 s_w1p[450];
    __shared__ __align__(16) float2 s_w2p[2400];
    __shared__ float s_b1[6], s_b2[16];
    __shared__ __align__(16) float s_xf[2][400];
    __shared__ float hs[2][10];

    int tid = threadIdx.x;

    // =======================================================================
    // PREP PATH (blocks 0-79)
    // =======================================================================
    if (blockIdx.x < 80) {
        float* sW1c = &s_x[0][0];      // 3000 floats
        float* sS   = sW1c + 3000;     // 1200
        float* sb2p = sS + 1200;       // 84
        float* sT2c = sb2p + 84;       // 250
        float* sb3l = sT2c + 250;      // 10   (total 4544 <= 6912)

        int chain = blockIdx.x >> 4, chunk = blockIdx.x & 15;
        int j0 = chunk * 25;

        if (chain == 0 && tid < 12) g_last[chunk * 12 + tid] = -1;

        const float* W1 = chain ? (ew1 + (chain - 1) * 120 * 400) : sw1;
        const float* W2 = chain ? (ew2 + (chain - 1) * 84 * 120) : sw2;
        const float* W3 = chain ? (ew3 + (chain - 1) * 10 * 84) : sw3;
        const float* b1 = chain ? (eb1 + (chain - 1) * 120) : sb1;
        const float* b2 = chain ? (eb2 + (chain - 1) * 84) : sb2;
        const float* b3 = chain ? (eb3 + (chain - 1) * 10) : sb3;

        for (int i = tid; i < 3000; i += 192) {
            int row = i / 25, col = i - row * 25;
            sW1c[i] = W1[row * 400 + j0 + col];
        }

        for (int p = tid; p < 1200; p += 192) {
            int o = p / 120, k = p - o * 120;
            float s = 0.f;
            const float* w3r = W3 + o * 84;
            for (int m = 0; m < 84; m++) s = fmaf(w3r[m], W2[m * 120 + k], s);
            sS[p] = s;
        }
        if (tid < 84) {
            float s = b2[tid];
            const float* r = W2 + tid * 120;
            for (int k = 0; k < 120; k++) s = fmaf(r[k], b1[k], s);
            sb2p[tid] = s;
        }
        __syncthreads();

        if (tid < 10) {
            float s = b3[tid];
            const float* r = W3 + tid * 84;
            for (int m = 0; m < 84; m++) s = fmaf(r[m], sb2p[m], s);
            sb3l[tid] = s;
            if (chunk == 0) g_b3[chain * 10 + tid] = s;
        }
        __syncthreads();

        for (int t = tid; t < 250; t += 192) {
            int o = t / 25, jj = t - o * 25;
            float s = 0.f;
            const float* sr = sS + o * 120;
            for (int k = 0; k < 120; k++) s = fmaf(sr[k], sW1c[k * 25 + jj], s);
            g_T2[(chain * 10 + o) * 400 + j0 + jj] = s;
            sT2c[o * 25 + jj] = s;
        }
        __syncthreads();

        if (chain == 0) {
            __threadfence();
            __syncthreads();
            if (tid == 0) atomicAdd(&g_ready, 1);
        } else {
            int e = chain - 1;
            if (tid < 150) {
                int c = tid / 25, jj = tid - c * 25;
                float s = 0.f;
                const float* w4r = ew4 + e * 60 + c * 10;
#pragma unroll
                for (int k = 0; k < 10; k++) s = fmaf(w4r[k], sT2c[k * 25 + jj], s);
                g_We[(e * 6 + c) * 400 + j0 + jj] = s;
            }
            if (chunk == 0 && tid < 6) {
                float s = eb4[e * 6 + tid];
                const float* w4r = ew4 + e * 60 + tid * 10;
#pragma unroll
                for (int k = 0; k < 10; k++) s = fmaf(w4r[k], sb3l[k], s);
                g_be[e * 6 + tid] = s;
            }
        }
        return;
    }

    // =======================================================================
    // CONV PATH (blocks 80..): two images per block
    // =======================================================================
    int b0i = (blockIdx.x - 80) * 2;

    {
        const float4* xg = (const float4*)(x + (size_t)b0i * 3072);
        for (int g = tid; g < 1536; g += 192) {
            float4 v = xg[g];
            int im = g / 768, q = g - im * 768;
            int gr = q >> 3, c4 = q & 7;
            *(float4*)(s_x[im] + gr * 36 + c4 * 4) = v;
        }
    }
    for (int i = tid; i < 450; i += 192)  { float w = c1w[i]; s_w1p[i] = make_float2(w, w); }
    for (int i = tid; i < 2400; i += 192) { float w = c2w[i]; s_w2p[i] = make_float2(w, w); }
    if (tid < 6)  s_b1[tid] = c1b[tid];
    if (tid < 16) s_b2[tid] = c2b[tid];
    __syncthreads();

    // ---- conv1 + relu + pool: 336 tasks = (img, ch, pooled row, half) ----
#pragma unroll 1
    for (int t = tid; t < 336; t += 192) {
        int img = t / 168, rem = t % 168;
        int ch = rem / 28, rr = rem % 28, py = rr >> 1, h = rr & 1;
        u64 acc0[7], acc1[7];
#pragma unroll
        for (int j = 0; j < 7; j++) { acc0[j] = 0ull; acc1[j] = 0ull; }
        const float* xbase = s_x[img] + (2 * py) * 36 + 14 * h;
#pragma unroll 1
        for (int ic = 0; ic < 3; ic++) {
            const float2* wb = s_w1p + (ch * 3 + ic) * 25;
            u64 wv[5][5];
#pragma unroll
            for (int xr = 0; xr < 6; xr++) {
                const u64* rp = (const u64*)(xbase + ic * (32 * 36) + xr * 36);
                u64 pe[9]; float xl[9], xh[9];
#pragma unroll
                for (int m = 0; m < 9; m++) { pe[m] = rp[m]; upk(pe[m], xl[m], xh[m]); }
                u64 po[8];
#pragma unroll
                for (int m = 0; m < 8; m++) po[m] = pk(xh[m], xl[m + 1]);
                if (xr < 5) {
#pragma unroll
                    for (int k = 0; k < 5; k++) wv[xr][k] = *(const u64*)&wb[xr * 5 + k];
#pragma unroll
                    for (int kx = 0; kx < 5; kx++) {
                        u64 w = wv[xr][kx];
#pragma unroll
                        for (int j = 0; j < 7; j++)
                            acc0[j] = fma2(w, (kx & 1) ? po[j + (kx >> 1)] : pe[j + (kx >> 1)], acc0[j]);
                    }
                }
                if (xr >= 1) {
#pragma unroll
                    for (int kx = 0; kx < 5; kx++) {
                        u64 w = wv[xr - 1][kx];
#pragma unroll
                        for (int j = 0; j < 7; j++)
                            acc1[j] = fma2(w, (kx & 1) ? po[j + (kx >> 1)] : pe[j + (kx >> 1)], acc1[j]);
                    }
                }
            }
        }
        float bv = s_b1[ch];
        float* yrow = s_y1[img] + (ch * 14 + py) * 20 + 7 * h;
#pragma unroll
        for (int j = 0; j < 7; j++) {
            float a0, a1, c0, c1;
            upk(acc0[j], a0, a1); upk(acc1[j], c0, c1);
            float m = fmaxf(fmaxf(a0, a1), fmaxf(c0, c1)) + bv;
            yrow[j] = fmaxf(m, 0.f);
        }
    }
    __syncthreads();

    // ---- conv2 full depth: 160 tasks = (img, ch, pooled row) ----
    if (tid < 160) {
        int img = tid / 80;
        int r2 = tid % 80, ch2 = r2 / 5, py2 = r2 % 5;
        u64 b0[5], b1[5];
#pragma unroll
        for (int j = 0; j < 5; j++) { b0[j] = 0ull; b1[j] = 0ull; }
#pragma unroll 1
        for (int ic = 0; ic < 6; ic++) {
            const float2* wb = s_w2p + (ch2 * 6 + ic) * 25;
            u64 wv[5][5];
#pragma unroll
            for (int xr = 0; xr < 6; xr++) {
                const u64* rp = (const u64*)(s_y1[img] + (ic * 14 + 2 * py2 + xr) * 20);
                u64 pe[7]; float xl[7], xh[7];
#pragma unroll
                for (int m = 0; m < 7; m++) { pe[m] = rp[m]; upk(pe[m], xl[m], xh[m]); }
                u64 po[6];
#pragma unroll
                for (int m = 0; m < 6; m++) po[m] = pk(xh[m], xl[m + 1]);
                if (xr < 5) {
#pragma unroll
                    for (int k = 0; k < 5; k++) wv[xr][k] = *(const u64*)&wb[xr * 5 + k];
#pragma unroll
                    for (int kx = 0; kx < 5; kx++) {
                        u64 w = wv[xr][kx];
#pragma unroll
                        for (int j = 0; j < 5; j++)
                            b0[j] = fma2(w, (kx & 1) ? po[j + (kx >> 1)] : pe[j + (kx >> 1)], b0[j]);
                    }
                }
                if (xr >= 1) {
#pragma unroll
                    for (int kx = 0; kx < 5; kx++) {
                        u64 w = wv[xr - 1][kx];
#pragma unroll
                        for (int j = 0; j < 5; j++)
                            b1[j] = fma2(w, (kx & 1) ? po[j + (kx >> 1)] : pe[j + (kx >> 1)], b1[j]);
                    }
                }
            }
        }
        float bv = s_b2[ch2];
        float* xfp = s_xf[img] + ch2 * 25 + py2 * 5;
        float* gxf = g_xf + (size_t)(b0i + img) * 400 + ch2 * 25 + py2 * 5;
#pragma unroll
        for (int j = 0; j < 5; j++) {
            float a0, a1, c0, c1;
            upk(b0[j], a0, a1); upk(b1[j], c0, c1);
            float v = fmaxf(fmaxf(a0, a1), fmaxf(c0, c1)) + bv;
            v = fmaxf(v, 0.f);
            xfp[j] = v; gxf[j] = v;
        }
    }

    // ---- wait for chain-0 prep (usually already done by now) ----
    if (tid == 0) {
        while (atomicAdd(&g_ready, 0) < 16) __nanosleep(200);
        __threadfence();
    }
    __syncthreads();

    // ---- h = Ws @ xf + bs : 10 outputs x 16 lanes = 160 threads;
    //      ONE pass over T2 (float4, coalesced) serves BOTH images ----
    if (tid < 160) {
        int o = tid >> 4, l = tid & 15;
        const float4* wr4 = (const float4*)(g_T2 + o * 400);
        const float4* x04 = (const float4*)s_xf[0];
        const float4* x14 = (const float4*)s_xf[1];
        float sa = 0.f, sb = 0.f;
#pragma unroll
        for (int it = 0; it < 7; it++) {
            int f = l + it * 16;
            if (f < 100) {
                float4 wq = wr4[f];
                float4 xa = x04[f];
                float4 xb = x14[f];
                sa = fmaf(wq.x, xa.x, sa); sa = fmaf(wq.y, xa.y, sa);
                sa = fmaf(wq.z, xa.z, sa); sa = fmaf(wq.w, xa.w, sa);
                sb = fmaf(wq.x, xb.x, sb); sb = fmaf(wq.y, xb.y, sb);
                sb = fmaf(wq.z, xb.z, sb); sb = fmaf(wq.w, xb.w, sb);
            }
        }
        sa += __shfl_down_sync(0xffffffffu, sa, 8, 16);
        sa += __shfl_down_sync(0xffffffffu, sa, 4, 16);
        sa += __shfl_down_sync(0xffffffffu, sa, 2, 16);
        sa += __shfl_down_sync(0xffffffffu, sa, 1, 16);
        sb += __shfl_down_sync(0xffffffffu, sb, 8, 16);
        sb += __shfl_down_sync(0xffffffffu, sb, 4, 16);
        sb += __shfl_down_sync(0xffffffffu, sb, 2, 16);
        sb += __shfl_down_sync(0xffffffffu, sb, 1, 16);
        if (l == 0) {
            float bv = g_b3[o];
            hs[0][o] = sa + bv;
            hs[1][o] = sb + bv;
        }
    }
    __syncthreads();

    // ---- shapes + argmax + routing: 2 threads (one per image) ----
    if (tid < 2) {
        int img = tid, b = b0i + img;
        float sh[4];
#pragma unroll
        for (int c = 0; c < 4; c++) {
            float s = sb4[c];
#pragma unroll
            for (int o = 0; o < 10; o++)
                s = fmaf(fmaxf(hs[img][o], 0.f), sw4[c * 10 + o], s);
            sh[c] = s;
            out[(size_t)b * 4 + c] = s;
        }
        int pred = 0;
        float best = sh[0];
#pragma unroll
        for (int k = 1; k < 4; k++)
            if (sh[k] > best) { best = sh[k]; pred = k; }
        const int widths[4] = {3, 5, 6, 5};
        int w = widths[pred];
        int val = (b << 2) | pred;
        int slot = b & 31;
        for (int c = 0; c < w; c++) atomicMax(&g_last[c * 32 + slot], val);
    }
}

// ---------------------------------------------------------------------------
// k_out: ONE WARP PER IMAGE, 512 threads = 16 warps = 16 images per block.
// xf PREFETCHED into registers BEFORE the wsel staging + barrier, so DRAM
// latency overlaps staging. xor-shuffle reduce, lane 0 writes. Resets g_ready.
// ---------------------------------------------------------------------------
__global__ void __launch_bounds__(512)
k_out(float* __restrict__ out) {
    __shared__ __align__(16) float wsel[6 * 400];
    __shared__ float bsel[6];
    __shared__ int   psel[6];
    int tid = threadIdx.x, wid = tid >> 5, lid = tid & 31;

    // ---- prefetch this warp's image features FIRST (independent loads) ----
    int b = blockIdx.x * 16 + wid;
    const float4* xfp = (const float4*)(g_xf + (size_t)b * 400);
    float4 xv[4];
#pragma unroll
    for (int it = 0; it < 4; it++) {
        int f = lid + it * 32;
        xv[it] = (f < 100) ? xfp[f] : make_float4(0.f, 0.f, 0.f, 0.f);
    }

    if (blockIdx.x == 0 && tid == 0) g_ready = 0;   // reset for next graph replay
    if (tid < 6) {
        int mx = -1;
#pragma unroll
        for (int s = 0; s < 32; s++) mx = max(mx, g_last[tid * 32 + s]);
        psel[tid] = mx;
        bsel[tid] = (mx >= 0) ? g_be[(mx & 3) * 6 + tid] : 0.f;
    }
    __syncthreads();
    for (int idx = tid; idx < 2400; idx += 512) {
        int c = idx / 400, j = idx - c * 400;
        int p = psel[c];
        wsel[idx] = (p >= 0) ? g_We[((p & 3) * 6 + c) * 400 + j] : 0.f;
    }
    __syncthreads();

    const float4* wv4 = (const float4*)wsel;
    float s[6] = {0.f, 0.f, 0.f, 0.f, 0.f, 0.f};
#pragma unroll
    for (int it = 0; it < 4; it++) {
        int f = lid + it * 32;
        if (f < 100) {
#pragma unroll
            for (int c = 0; c < 6; c++) {
                float4 wq = wv4[c * 100 + f];
                s[c] = fmaf(xv[it].x, wq.x, s[c]);
                s[c] = fmaf(xv[it].y, wq.y, s[c]);
                s[c] = fmaf(xv[it].z, wq.z, s[c]);
                s[c] = fmaf(xv[it].w, wq.w, s[c]);
            }
        }
    }
#pragma unroll
    for (int c = 0; c < 6; c++) {
        s[c] += __shfl_xor_sync(0xffffffffu, s[c], 16);
        s[c] += __shfl_xor_sync(0xffffffffu, s[c], 8);
        s[c] += __shfl_xor_sync(0xffffffffu, s[c], 4);
        s[c] += __shfl_xor_sync(0xffffffffu, s[c], 2);
        s[c] += __shfl_xor_sync(0xffffffffu, s[c], 1);
    }
    if (lid == 0) {
        float* op = out + (size_t)B_TOTAL * 4 + (size_t)b * 6;
#pragma unroll
        for (int c = 0; c < 6; c++) op[c] = s[c] + bsel[c];
    }
}

// ---------------------------------------------------------------------------
extern "C" void kernel_launch(void* const* d_in, const int* in_sizes, int n_in,
                              void* d_out, int out_size) {
    const float* x    = (const float*)d_in[0];
    const float* c1w  = (const float*)d_in[1];
    const float* c1b  = (const float*)d_in[2];
    const float* c2w  = (const float*)d_in[3];
    const float* c2b  = (const float*)d_in[4];
    const float* sw1  = (const float*)d_in[5];
    const float* sb1  = (const float*)d_in[6];
    const float* sw2  = (const float*)d_in[7];
    const float* sb2  = (const float*)d_in[8];
    const float* sw3  = (const float*)d_in[9];
    const float* sb3  = (const float*)d_in[10];
    const float* sw4  = (const float*)d_in[11];
    const float* sb4  = (const float*)d_in[12];
    const float* ew1  = (const float*)d_in[13];
    const float* eb1  = (const float*)d_in[14];
    const float* ew2  = (const float*)d_in[15];
    const float* eb2  = (const float*)d_in[16];
    const float* ew3  = (const float*)d_in[17];
    const float* eb3  = (const float*)d_in[18];
    const float* ew4  = (const float*)d_in[19];
    const float* eb4  = (const float*)d_in[20];
    float* out = (float*)d_out;

    k_main<<<80 + B_TOTAL / 2, 192>>>(x, c1w, c1b, c2w, c2b, sw4, sb4,
                                      sw1, sb1, sw2, sb2, sw3, sb3,
                                      ew1, eb1, ew2, eb2, ew3, eb3, ew4, eb4,
                                      out);
    k_out<<<B_TOTAL / 16, 512>>>(out);
}

// round 17
// speedup vs baseline: 1.0196x; 1.0090x over previous
#include <cuda_runtime.h>
#include <cuda_bf16.h>

// ---------------------------------------------------------------------------
// RtoVMainModel. Convs per image in smem (packed f32x2 FMA); linear heads
// collapsed at runtime (S=W3@W2, T2=S@W1, We=ew4@T2) by PREP BLOCKS fused
// into the main grid (blocks 0-79). Conv blocks (80..8271) spin on a 16-count
// flag before the head phase. k_out: warp handles TWO images, xf prefetched.
// d_out layout: [shapes (B*4) | out (B*6)] float32
// ---------------------------------------------------------------------------

#define B_TOTAL 16384
typedef unsigned long long u64;

__device__ __forceinline__ u64 pk(float lo, float hi) {
    u64 r; asm("mov.b64 %0, {%1, %2};" : "=l"(r) : "f"(lo), "f"(hi)); return r;
}
__device__ __forceinline__ void upk(u64 p, float& lo, float& hi) {
    asm("mov.b64 {%0, %1}, %2;" : "=f"(lo), "=f"(hi) : "l"(p));
}
__device__ __forceinline__ u64 fma2(u64 a, u64 b, u64 c) {
    u64 d; asm("fma.rn.f32x2 %0, %1, %2, %3;" : "=l"(d) : "l"(a), "l"(b), "l"(c)); return d;
}

// scratch (device globals: no allocation allowed)
__device__ float g_T2[5 * 10 * 400];     // chain 0 = shapes head (10x400)
__device__ float g_b3[5 * 10];
__device__ float g_We[4 * 6 * 400];      // expert collapsed rows
__device__ float g_be[4 * 6];            // expert collapsed bias (incl eb4)
__device__ float g_xf[B_TOTAL * 400];    // conv features
__device__ int   g_last[6 * 32];         // routing slots [col][b&31]
__device__ int   g_ready;                // chain-0 prep completion counter

// ---------------------------------------------------------------------------
// Fused kernel: blocks 0-79 = prep (5 chains x 16 column-chunks);
// blocks 80..8271 = conv path, 2 images each.
// ---------------------------------------------------------------------------
__global__ void __launch_bounds__(192, 3)
k_main(const float* __restrict__ x,
       const float* __restrict__ c1w, const float* __restrict__ c1b,
       const float* __restrict__ c2w, const float* __restrict__ c2b,
       const float* __restrict__ sw4, const float* __restrict__ sb4,
       const float* __restrict__ sw1, const float* __restrict__ sb1,
       const float* __restrict__ sw2, const float* __restrict__ sb2,
       const float* __restrict__ sw3, const float* __restrict__ sb3,
       const float* __restrict__ ew1, const float* __restrict__ eb1,
       const float* __restrict__ ew2, const float* __restrict__ eb2,
       const float* __restrict__ ew3, const float* __restrict__ eb3,
       const float* __restrict__ ew4, const float* __restrict__ eb4,
       float* __restrict__ out) {
    __shared__ __align__(16) float  s_x[2][3 * 32 * 36];
    __shared__ __align__(16) float  s_y1[2][6 * 14 * 20];
    __shared__ __align__(16) float2 s_w1p[450];
    __shared__ __align__(16) float2 s_w2p[2400];
    __shared__ float s_b1[6], s_b2[16];
    __shared__ __align__(16) float s_xf[2][400];
    __shared__ float hs[2][10];

    int tid = threadIdx.x;

    // =======================================================================
    // PREP PATH (blocks 0-79)
    // =======================================================================
    if (blockIdx.x < 80) {
        float* sW1c = &s_x[0][0];      // 3000 floats
        float* sS   = sW1c + 3000;     // 1200
        float* sb2p = sS + 1200;       // 84
        float* sT2c = sb2p + 84;       // 250
        float* sb3l = sT2c + 250;      // 10   (total 4544 <= 6912)

        int chain = blockIdx.x >> 4, chunk = blockIdx.x & 15;
        int j0 = chunk * 25;

        if (chain == 0 && tid < 12) g_last[chunk * 12 + tid] = -1;

        const float* W1 = chain ? (ew1 + (chain - 1) * 120 * 400) : sw1;
        const float* W2 = chain ? (ew2 + (chain - 1) * 84 * 120) : sw2;
        const float* W3 = chain ? (ew3 + (chain - 1) * 10 * 84) : sw3;
        const float* b1 = chain ? (eb1 + (chain - 1) * 120) : sb1;
        const float* b2 = chain ? (eb2 + (chain - 1) * 84) : sb2;
        const float* b3 = chain ? (eb3 + (chain - 1) * 10) : sb3;

        for (int i = tid; i < 3000; i += 192) {
            int row = i / 25, col = i - row * 25;
            sW1c[i] = W1[row * 400 + j0 + col];
        }

        for (int p = tid; p < 1200; p += 192) {
            int o = p / 120, k = p - o * 120;
            float s = 0.f;
            const float* w3r = W3 + o * 84;
            for (int m = 0; m < 84; m++) s = fmaf(w3r[m], W2[m * 120 + k], s);
            sS[p] = s;
        }
        if (tid < 84) {
            float s = b2[tid];
            const float* r = W2 + tid * 120;
            for (int k = 0; k < 120; k++) s = fmaf(r[k], b1[k], s);
            sb2p[tid] = s;
        }
        __syncthreads();

        if (tid < 10) {
            float s = b3[tid];
            const float* r = W3 + tid * 84;
            for (int m = 0; m < 84; m++) s = fmaf(r[m], sb2p[m], s);
            sb3l[tid] = s;
            if (chunk == 0) g_b3[chain * 10 + tid] = s;
        }
        __syncthreads();

        for (int t = tid; t < 250; t += 192) {
            int o = t / 25, jj = t - o * 25;
            float s = 0.f;
            const float* sr = sS + o * 120;
            for (int k = 0; k < 120; k++) s = fmaf(sr[k], sW1c[k * 25 + jj], s);
            g_T2[(chain * 10 + o) * 400 + j0 + jj] = s;
            sT2c[o * 25 + jj] = s;
        }
        __syncthreads();

        if (chain == 0) {
            __threadfence();
            __syncthreads();
            if (tid == 0) atomicAdd(&g_ready, 1);
        } else {
            int e = chain - 1;
            if (tid < 150) {
                int c = tid / 25, jj = tid - c * 25;
                float s = 0.f;
                const float* w4r = ew4 + e * 60 + c * 10;
#pragma unroll
                for (int k = 0; k < 10; k++) s = fmaf(w4r[k], sT2c[k * 25 + jj], s);
                g_We[(e * 6 + c) * 400 + j0 + jj] = s;
            }
            if (chunk == 0 && tid < 6) {
                float s = eb4[e * 6 + tid];
                const float* w4r = ew4 + e * 60 + tid * 10;
#pragma unroll
                for (int k = 0; k < 10; k++) s = fmaf(w4r[k], sb3l[k], s);
                g_be[e * 6 + tid] = s;
            }
        }
        return;
    }

    // =======================================================================
    // CONV PATH (blocks 80..): two images per block
    // =======================================================================
    int b0i = (blockIdx.x - 80) * 2;

    {
        const float4* xg = (const float4*)(x + (size_t)b0i * 3072);
        for (int g = tid; g < 1536; g += 192) {
            float4 v = xg[g];
            int im = g / 768, q = g - im * 768;
            int gr = q >> 3, c4 = q & 7;
            *(float4*)(s_x[im] + gr * 36 + c4 * 4) = v;
        }
    }
    for (int i = tid; i < 450; i += 192)  { float w = c1w[i]; s_w1p[i] = make_float2(w, w); }
    for (int i = tid; i < 2400; i += 192) { float w = c2w[i]; s_w2p[i] = make_float2(w, w); }
    if (tid < 6)  s_b1[tid] = c1b[tid];
    if (tid < 16) s_b2[tid] = c2b[tid];
    __syncthreads();

    // ---- conv1 + relu + pool: 336 tasks = (img, ch, pooled row, half) ----
#pragma unroll 1
    for (int t = tid; t < 336; t += 192) {
        int img = t / 168, rem = t % 168;
        int ch = rem / 28, rr = rem % 28, py = rr >> 1, h = rr & 1;
        u64 acc0[7], acc1[7];
#pragma unroll
        for (int j = 0; j < 7; j++) { acc0[j] = 0ull; acc1[j] = 0ull; }
        const float* xbase = s_x[img] + (2 * py) * 36 + 14 * h;
#pragma unroll 1
        for (int ic = 0; ic < 3; ic++) {
            const float2* wb = s_w1p + (ch * 3 + ic) * 25;
            u64 wv[5][5];
#pragma unroll
            for (int xr = 0; xr < 6; xr++) {
                const u64* rp = (const u64*)(xbase + ic * (32 * 36) + xr * 36);
                u64 pe[9]; float xl[9], xh[9];
#pragma unroll
                for (int m = 0; m < 9; m++) { pe[m] = rp[m]; upk(pe[m], xl[m], xh[m]); }
                u64 po[8];
#pragma unroll
                for (int m = 0; m < 8; m++) po[m] = pk(xh[m], xl[m + 1]);
                if (xr < 5) {
#pragma unroll
                    for (int k = 0; k < 5; k++) wv[xr][k] = *(const u64*)&wb[xr * 5 + k];
#pragma unroll
                    for (int kx = 0; kx < 5; kx++) {
                        u64 w = wv[xr][kx];
#pragma unroll
                        for (int j = 0; j < 7; j++)
                            acc0[j] = fma2(w, (kx & 1) ? po[j + (kx >> 1)] : pe[j + (kx >> 1)], acc0[j]);
                    }
                }
                if (xr >= 1) {
#pragma unroll
                    for (int kx = 0; kx < 5; kx++) {
                        u64 w = wv[xr - 1][kx];
#pragma unroll
                        for (int j = 0; j < 7; j++)
                            acc1[j] = fma2(w, (kx & 1) ? po[j + (kx >> 1)] : pe[j + (kx >> 1)], acc1[j]);
                    }
                }
            }
        }
        float bv = s_b1[ch];
        float* yrow = s_y1[img] + (ch * 14 + py) * 20 + 7 * h;
#pragma unroll
        for (int j = 0; j < 7; j++) {
            float a0, a1, c0, c1;
            upk(acc0[j], a0, a1); upk(acc1[j], c0, c1);
            float m = fmaxf(fmaxf(a0, a1), fmaxf(c0, c1)) + bv;
            yrow[j] = fmaxf(m, 0.f);
        }
    }
    __syncthreads();

    // ---- conv2 full depth: 160 tasks = (img, ch, pooled row) ----
    if (tid < 160) {
        int img = tid / 80;
        int r2 = tid % 80, ch2 = r2 / 5, py2 = r2 % 5;
        u64 b0[5], b1[5];
#pragma unroll
        for (int j = 0; j < 5; j++) { b0[j] = 0ull; b1[j] = 0ull; }
#pragma unroll 1
        for (int ic = 0; ic < 6; ic++) {
            const float2* wb = s_w2p + (ch2 * 6 + ic) * 25;
            u64 wv[5][5];
#pragma unroll
            for (int xr = 0; xr < 6; xr++) {
                const u64* rp = (const u64*)(s_y1[img] + (ic * 14 + 2 * py2 + xr) * 20);
                u64 pe[7]; float xl[7], xh[7];
#pragma unroll
                for (int m = 0; m < 7; m++) { pe[m] = rp[m]; upk(pe[m], xl[m], xh[m]); }
                u64 po[6];
#pragma unroll
                for (int m = 0; m < 6; m++) po[m] = pk(xh[m], xl[m + 1]);
                if (xr < 5) {
#pragma unroll
                    for (int k = 0; k < 5; k++) wv[xr][k] = *(const u64*)&wb[xr * 5 + k];
#pragma unroll
                    for (int kx = 0; kx < 5; kx++) {
                        u64 w = wv[xr][kx];
#pragma unroll
                        for (int j = 0; j < 5; j++)
                            b0[j] = fma2(w, (kx & 1) ? po[j + (kx >> 1)] : pe[j + (kx >> 1)], b0[j]);
                    }
                }
                if (xr >= 1) {
#pragma unroll
                    for (int kx = 0; kx < 5; kx++) {
                        u64 w = wv[xr - 1][kx];
#pragma unroll
                        for (int j = 0; j < 5; j++)
                            b1[j] = fma2(w, (kx & 1) ? po[j + (kx >> 1)] : pe[j + (kx >> 1)], b1[j]);
                    }
                }
            }
        }
        float bv = s_b2[ch2];
        float* xfp = s_xf[img] + ch2 * 25 + py2 * 5;
        float* gxf = g_xf + (size_t)(b0i + img) * 400 + ch2 * 25 + py2 * 5;
#pragma unroll
        for (int j = 0; j < 5; j++) {
            float a0, a1, c0, c1;
            upk(b0[j], a0, a1); upk(b1[j], c0, c1);
            float v = fmaxf(fmaxf(a0, a1), fmaxf(c0, c1)) + bv;
            v = fmaxf(v, 0.f);
            xfp[j] = v; gxf[j] = v;
        }
    }

    // ---- wait for chain-0 prep (usually already done by now) ----
    if (tid == 0) {
        while (atomicAdd(&g_ready, 0) < 16) __nanosleep(200);
        __threadfence();
    }
    __syncthreads();

    // ---- h = Ws @ xf + bs : 10 outputs x 16 lanes = 160 threads;
    //      ONE pass over T2 (float4, coalesced) serves BOTH images ----
    if (tid < 160) {
        int o = tid >> 4, l = tid & 15;
        const float4* wr4 = (const float4*)(g_T2 + o * 400);
        const float4* x04 = (const float4*)s_xf[0];
        const float4* x14 = (const float4*)s_xf[1];
        float sa = 0.f, sb = 0.f;
#pragma unroll
        for (int it = 0; it < 7; it++) {
            int f = l + it * 16;
            if (f < 100) {
                float4 wq = wr4[f];
                float4 xa = x04[f];
                float4 xb = x14[f];
                sa = fmaf(wq.x, xa.x, sa); sa = fmaf(wq.y, xa.y, sa);
                sa = fmaf(wq.z, xa.z, sa); sa = fmaf(wq.w, xa.w, sa);
                sb = fmaf(wq.x, xb.x, sb); sb = fmaf(wq.y, xb.y, sb);
                sb = fmaf(wq.z, xb.z, sb); sb = fmaf(wq.w, xb.w, sb);
            }
        }
        sa += __shfl_down_sync(0xffffffffu, sa, 8, 16);
        sa += __shfl_down_sync(0xffffffffu, sa, 4, 16);
        sa += __shfl_down_sync(0xffffffffu, sa, 2, 16);
        sa += __shfl_down_sync(0xffffffffu, sa, 1, 16);
        sb += __shfl_down_sync(0xffffffffu, sb, 8, 16);
        sb += __shfl_down_sync(0xffffffffu, sb, 4, 16);
        sb += __shfl_down_sync(0xffffffffu, sb, 2, 16);
        sb += __shfl_down_sync(0xffffffffu, sb, 1, 16);
        if (l == 0) {
            float bv = g_b3[o];
            hs[0][o] = sa + bv;
            hs[1][o] = sb + bv;
        }
    }
    __syncthreads();

    // ---- shapes + argmax + routing: 2 threads (one per image) ----
    if (tid < 2) {
        int img = tid, b = b0i + img;
        float sh[4];
#pragma unroll
        for (int c = 0; c < 4; c++) {
            float s = sb4[c];
#pragma unroll
            for (int o = 0; o < 10; o++)
                s = fmaf(fmaxf(hs[img][o], 0.f), sw4[c * 10 + o], s);
            sh[c] = s;
            out[(size_t)b * 4 + c] = s;
        }
        int pred = 0;
        float best = sh[0];
#pragma unroll
        for (int k = 1; k < 4; k++)
            if (sh[k] > best) { best = sh[k]; pred = k; }
        const int widths[4] = {3, 5, 6, 5};
        int w = widths[pred];
        int val = (b << 2) | pred;
        int slot = b & 31;
        for (int c = 0; c < w; c++) atomicMax(&g_last[c * 32 + slot], val);
    }
}

// ---------------------------------------------------------------------------
// k_out: each warp handles TWO images (16 warps = 32 images/block, grid 512).
// Both images' xf prefetched (8 LDG.128/lane in flight) BEFORE wsel staging,
// doubling bytes-in-flight vs one image. xor-shuffle reduce per image.
// Resets g_ready.
// ---------------------------------------------------------------------------
__global__ void __launch_bounds__(512)
k_out(float* __restrict__ out) {
    __shared__ __align__(16) float wsel[6 * 400];
    __shared__ float bsel[6];
    __shared__ int   psel[6];
    int tid = threadIdx.x, wid = tid >> 5, lid = tid & 31;

    // ---- prefetch BOTH images' features FIRST (8 independent loads) ----
    int b0 = blockIdx.x * 32 + wid * 2;
    const float4* xfp0 = (const float4*)(g_xf + (size_t)b0 * 400);
    const float4* xfp1 = (const float4*)(g_xf + (size_t)(b0 + 1) * 400);
    float4 xv0[4], xv1[4];
#pragma unroll
    for (int it = 0; it < 4; it++) {
        int f = lid + it * 32;
        bool ok = (f < 100);
        xv0[it] = ok ? xfp0[f] : make_float4(0.f, 0.f, 0.f, 0.f);
        xv1[it] = ok ? xfp1[f] : make_float4(0.f, 0.f, 0.f, 0.f);
    }

    if (blockIdx.x == 0 && tid == 0) g_ready = 0;   // reset for next graph replay
    if (tid < 6) {
        int mx = -1;
#pragma unroll
        for (int s = 0; s < 32; s++) mx = max(mx, g_last[tid * 32 + s]);
        psel[tid] = mx;
        bsel[tid] = (mx >= 0) ? g_be[(mx & 3) * 6 + tid] : 0.f;
    }
    __syncthreads();
    for (int idx = tid; idx < 2400; idx += 512) {
        int c = idx / 400, j = idx - c * 400;
        int p = psel[c];
        wsel[idx] = (p >= 0) ? g_We[((p & 3) * 6 + c) * 400 + j] : 0.f;
    }
    __syncthreads();

    const float4* wv4 = (const float4*)wsel;
    float s0[6] = {0.f, 0.f, 0.f, 0.f, 0.f, 0.f};
    float s1[6] = {0.f, 0.f, 0.f, 0.f, 0.f, 0.f};
#pragma unroll
    for (int it = 0; it < 4; it++) {
        int f = lid + it * 32;
        if (f < 100) {
#pragma unroll
            for (int c = 0; c < 6; c++) {
                float4 wq = wv4[c * 100 + f];
                s0[c] = fmaf(xv0[it].x, wq.x, s0[c]);
                s0[c] = fmaf(xv0[it].y, wq.y, s0[c]);
                s0[c] = fmaf(xv0[it].z, wq.z, s0[c]);
                s0[c] = fmaf(xv0[it].w, wq.w, s0[c]);
                s1[c] = fmaf(xv1[it].x, wq.x, s1[c]);
                s1[c] = fmaf(xv1[it].y, wq.y, s1[c]);
                s1[c] = fmaf(xv1[it].z, wq.z, s1[c]);
                s1[c] = fmaf(xv1[it].w, wq.w, s1[c]);
            }
        }
    }
#pragma unroll
    for (int c = 0; c < 6; c++) {
        s0[c] += __shfl_xor_sync(0xffffffffu, s0[c], 16);
        s0[c] += __shfl_xor_sync(0xffffffffu, s0[c], 8);
        s0[c] += __shfl_xor_sync(0xffffffffu, s0[c], 4);
        s0[c] += __shfl_xor_sync(0xffffffffu, s0[c], 2);
        s0[c] += __shfl_xor_sync(0xffffffffu, s0[c], 1);
        s1[c] += __shfl_xor_sync(0xffffffffu, s1[c], 16);
        s1[c] += __shfl_xor_sync(0xffffffffu, s1[c], 8);
        s1[c] += __shfl_xor_sync(0xffffffffu, s1[c], 4);
        s1[c] += __shfl_xor_sync(0xffffffffu, s1[c], 2);
        s1[c] += __shfl_xor_sync(0xffffffffu, s1[c], 1);
    }
    if (lid == 0) {
        float* op = out + (size_t)B_TOTAL * 4 + (size_t)b0 * 6;
#pragma unroll
        for (int c = 0; c < 6; c++) op[c] = s0[c] + bsel[c];
#pragma unroll
        for (int c = 0; c < 6; c++) op[6 + c] = s1[c] + bsel[c];
    }
}

// ---------------------------------------------------------------------------
extern "C" void kernel_launch(void* const* d_in, const int* in_sizes, int n_in,
                              void* d_out, int out_size) {
    const float* x    = (const float*)d_in[0];
    const float* c1w  = (const float*)d_in[1];
    const float* c1b  = (const float*)d_in[2];
    const float* c2w  = (const float*)d_in[3];
    const float* c2b  = (const float*)d_in[4];
    const float* sw1  = (const float*)d_in[5];
    const float* sb1  = (const float*)d_in[6];
    const float* sw2  = (const float*)d_in[7];
    const float* sb2  = (const float*)d_in[8];
    const float* sw3  = (const float*)d_in[9];
    const float* sb3  = (const float*)d_in[10];
    const float* sw4  = (const float*)d_in[11];
    const float* sb4  = (const float*)d_in[12];
    const float* ew1  = (const float*)d_in[13];
    const float* eb1  = (const float*)d_in[14];
    const float* ew2  = (const float*)d_in[15];
    const float* eb2  = (const float*)d_in[16];
    const float* ew3  = (const float*)d_in[17];
    const float* eb3  = (const float*)d_in[18];
    const float* ew4  = (const float*)d_in[19];
    const float* eb4  = (const float*)d_in[20];
    float* out = (float*)d_out;

    k_main<<<80 + B_TOTAL / 2, 192>>>(x, c1w, c1b, c2w, c2b, sw4, sb4,
                                      sw1, sb1, sw2, sb2, sw3, sb3,
                                      ew1, eb1, ew2, eb2, ew3, eb3, ew4, eb4,
                                      out);
    k_out<<<B_TOTAL / 32, 512>>>(out);
}